// round 1
// baseline (speedup 1.0000x reference)
#include <cuda_runtime.h>
#include <cuda_bf16.h>
#include <math.h>

// Problem constants (fixed shapes per reference)
namespace {
constexpr int T_  = 4096;
constexpr int D_  = 1024;
constexpr int E_  = 8;
constexpr int F_  = 2816;
constexpr int K_  = 2;
constexpr int NP  = T_ * K_;      // 8192 (token, k) pairs
constexpr int N1  = 2 * F_;       // 5632 gate+up columns
constexpr int BM  = 128, BN = 128, BK = 16;
constexpr int MAXTILES = 72;      // sum ceil(cnt_e/128) <= 64 + 7 = 71
}

// ---------------- device scratch (static, allocation-free) ----------------
__device__ float g_h[(size_t)NP * N1];        // gate_up activations (184.5 MB)
__device__ float g_act[(size_t)NP * F_];      // silu(gate)*up       (92 MB)
__device__ float g_pairout[(size_t)NP * D_];  // per-pair outputs    (33.5 MB)

__device__ int g_cnt[E_];
__device__ int g_off[E_ + 1];
__device__ int g_pair_e[NP];
__device__ int g_pair_slot[NP];
__device__ int g_rowtok[NP];    // compact row -> token id
__device__ int g_rowpair[NP];   // compact row -> pair id
__device__ int g_tile_e[MAXTILES];
__device__ int g_tile_r0[MAXTILES];
__device__ int g_tile_rows[MAXTILES];
__device__ int g_ntiles;

// ---------------- routing ----------------
__global__ void k_zero() {
    if (threadIdx.x < E_) g_cnt[threadIdx.x] = 0;
}

__global__ void k_assign(const int* __restrict__ ids) {
    int p = blockIdx.x * 256 + threadIdx.x;
    if (p >= NP) return;
    int e = ids[p];
    e = e < 0 ? 0 : (e >= E_ ? E_ - 1 : e);
    g_pair_e[p] = e;
    g_pair_slot[p] = atomicAdd(&g_cnt[e], 1);
}

__global__ void k_tiles() {
    // single thread: prefix sum over E=8 + tile descriptors
    int off = 0;
    g_off[0] = 0;
    for (int e = 0; e < E_; e++) { off += g_cnt[e]; g_off[e + 1] = off; }
    int nt = 0;
    for (int e = 0; e < E_; e++) {
        for (int r0 = g_off[e]; r0 < g_off[e + 1]; r0 += BM) {
            g_tile_e[nt] = e;
            g_tile_r0[nt] = r0;
            int rem = g_off[e + 1] - r0;
            g_tile_rows[nt] = rem < BM ? rem : BM;
            nt++;
        }
    }
    g_ntiles = nt;
}

__global__ void k_rows() {
    int p = blockIdx.x * 256 + threadIdx.x;
    if (p >= NP) return;
    int gr = g_off[g_pair_e[p]] + g_pair_slot[p];
    g_rowtok[gr]  = p >> 1;   // K_ == 2
    g_rowpair[gr] = p;
}

// ---------------- tiled fp32 GEMM (double-buffered SMEM) ----------------
// G1: h[row, n]      = sum_k x[tok(row), k]      * gate_up[e, n, k]   (KDIM=D_,  NDIM=N1)
// G2: pairout[pr, n] = sum_k act[row, k]         * down[e, n, k]      (KDIM=F_,  NDIM=D_)
template <bool G1>
__global__ void __launch_bounds__(256, 2)
moe_gemm(const float* __restrict__ Ain, const float* __restrict__ B0) {
    constexpr int KDIM = G1 ? D_ : F_;
    constexpr int NDIM = G1 ? N1 : D_;
    constexpr int NKT  = KDIM / BK;

    int bt = blockIdx.y;
    if (bt >= g_ntiles) return;
    const int bn0  = blockIdx.x * BN;
    const int e    = g_tile_e[bt];
    const int row0 = g_tile_r0[bt];
    const int rows = g_tile_rows[bt];

    const float* __restrict__ A0 = G1 ? Ain : (const float*)g_act;
    const float* __restrict__ Bp = B0 + (size_t)e * NDIM * KDIM;
    float* __restrict__ Cb = G1 ? (float*)g_h : (float*)g_pairout;

    __shared__ __align__(16) float As[2][BK][BM];
    __shared__ __align__(16) float Bs[2][BK][BN];
    __shared__ int s_map[BM];   // A-row index into A0 (-1 = pad)
    __shared__ int s_out[BM];   // C-row index        (-1 = pad)

    const int tid = threadIdx.x;
    if (tid < BM) {
        int amap = -1, omap = -1;
        if (tid < rows) {
            if (G1) { amap = g_rowtok[row0 + tid]; omap = row0 + tid; }
            else    { amap = row0 + tid;           omap = g_rowpair[row0 + tid]; }
        }
        s_map[tid] = amap;
        s_out[tid] = omap;
    }
    __syncthreads();

    const int row_a = tid >> 2;      // 0..63 (second chunk at +64)
    const int kq    = tid & 3;       // float4 index within BK

    auto loadA = [&](int kt, int ridx) -> float4 {
        int ar = s_map[ridx];
        if (ar < 0) return make_float4(0.f, 0.f, 0.f, 0.f);
        return *(const float4*)(A0 + (size_t)ar * KDIM + kt * BK + kq * 4);
    };
    auto loadB = [&](int kt, int ridx) -> float4 {
        return *(const float4*)(Bp + (size_t)(bn0 + ridx) * KDIM + kt * BK + kq * 4);
    };

    float4 pa0 = loadA(0, row_a), pa1 = loadA(0, row_a + 64);
    float4 pb0 = loadB(0, row_a), pb1 = loadB(0, row_a + 64);

    auto stash = [&](int buf) {
        As[buf][kq * 4 + 0][row_a] = pa0.x;  As[buf][kq * 4 + 1][row_a] = pa0.y;
        As[buf][kq * 4 + 2][row_a] = pa0.z;  As[buf][kq * 4 + 3][row_a] = pa0.w;
        As[buf][kq * 4 + 0][row_a + 64] = pa1.x;  As[buf][kq * 4 + 1][row_a + 64] = pa1.y;
        As[buf][kq * 4 + 2][row_a + 64] = pa1.z;  As[buf][kq * 4 + 3][row_a + 64] = pa1.w;
        Bs[buf][kq * 4 + 0][row_a] = pb0.x;  Bs[buf][kq * 4 + 1][row_a] = pb0.y;
        Bs[buf][kq * 4 + 2][row_a] = pb0.z;  Bs[buf][kq * 4 + 3][row_a] = pb0.w;
        Bs[buf][kq * 4 + 0][row_a + 64] = pb1.x;  Bs[buf][kq * 4 + 1][row_a + 64] = pb1.y;
        Bs[buf][kq * 4 + 2][row_a + 64] = pb1.z;  Bs[buf][kq * 4 + 3][row_a + 64] = pb1.w;
    };
    stash(0);
    __syncthreads();

    const int m0  = (tid >> 4) * 4;  // row offset within [0,64)
    const int n0t = (tid & 15) * 4;  // col offset within [0,64)

    float acc[8][8];
#pragma unroll
    for (int i = 0; i < 8; i++)
#pragma unroll
        for (int j = 0; j < 8; j++) acc[i][j] = 0.f;

    int buf = 0;
    for (int kt = 0; kt < NKT; ++kt) {
        if (kt + 1 < NKT) {
            pa0 = loadA(kt + 1, row_a); pa1 = loadA(kt + 1, row_a + 64);
            pb0 = loadB(kt + 1, row_a); pb1 = loadB(kt + 1, row_a + 64);
        }
#pragma unroll
        for (int kk = 0; kk < BK; ++kk) {
            float a[8], b[8];
            *(float4*)(a)     = *(const float4*)&As[buf][kk][m0];
            *(float4*)(a + 4) = *(const float4*)&As[buf][kk][m0 + 64];
            *(float4*)(b)     = *(const float4*)&Bs[buf][kk][n0t];
            *(float4*)(b + 4) = *(const float4*)&Bs[buf][kk][n0t + 64];
#pragma unroll
            for (int i = 0; i < 8; i++)
#pragma unroll
                for (int j = 0; j < 8; j++) acc[i][j] += a[i] * b[j];
        }
        if (kt + 1 < NKT) {
            stash(buf ^ 1);
            __syncthreads();
            buf ^= 1;
        }
    }

#pragma unroll
    for (int i = 0; i < 8; i++) {
        int gm = (i < 4) ? (m0 + i) : (64 + m0 + (i - 4));
        int orow = s_out[gm];
        if (orow < 0) continue;
        float* cp = Cb + (size_t)orow * NDIM + bn0;
        *(float4*)(cp + n0t)      = make_float4(acc[i][0], acc[i][1], acc[i][2], acc[i][3]);
        *(float4*)(cp + n0t + 64) = make_float4(acc[i][4], acc[i][5], acc[i][6], acc[i][7]);
    }
}

// ---------------- SiLU(gate) * up ----------------
__global__ void k_act() {
    int f = blockIdx.x * 256 + threadIdx.x;   // grid.x = F_/256 = 11
    int r = blockIdx.y;                        // 0..NP-1
    float gv = g_h[(size_t)r * N1 + f];
    float uv = g_h[(size_t)r * N1 + F_ + f];
    float s  = gv / (1.0f + expf(-gv));
    g_act[(size_t)r * F_ + f] = s * uv;
}

// ---------------- weighted combine (deterministic, no atomics) ----------------
__global__ void k_combine(const float* __restrict__ tw, float* __restrict__ out) {
    int d = blockIdx.x * 256 + threadIdx.x;   // grid.x = D_/256 = 4
    int t = blockIdx.y;
    float w0 = tw[t * 2 + 0];
    float w1 = tw[t * 2 + 1];
    out[(size_t)t * D_ + d] =
        w0 * g_pairout[(size_t)(2 * t + 0) * D_ + d] +
        w1 * g_pairout[(size_t)(2 * t + 1) * D_ + d];
}

// ---------------- launch ----------------
extern "C" void kernel_launch(void* const* d_in, const int* in_sizes, int n_in,
                              void* d_out, int out_size) {
    const float* x   = (const float*)d_in[0];   // [T, D]
    const float* gup = (const float*)d_in[1];   // [E, 2F, D]
    const float* dwn = (const float*)d_in[2];   // [E, D, F]
    const float* tw  = (const float*)d_in[3];   // [T, K]
    const int*   ids = (const int*)d_in[4];     // [T, K]
    float* out = (float*)d_out;                 // [T, D]

    k_zero<<<1, 32>>>();
    k_assign<<<NP / 256, 256>>>(ids);
    k_tiles<<<1, 1>>>();
    k_rows<<<NP / 256, 256>>>();

    moe_gemm<true ><<<dim3(N1 / BN, MAXTILES), 256>>>(x, gup);
    k_act<<<dim3(F_ / 256, NP), 256>>>();
    moe_gemm<false><<<dim3(D_ / BN, MAXTILES), 256>>>(x /*unused*/, dwn);

    k_combine<<<dim3(D_ / 256, T_), 256>>>(tw, out);
}

// round 3
// speedup vs baseline: 2.0845x; 2.0845x over previous
#include <cuda_runtime.h>
#include <cuda_bf16.h>
#include <math.h>
#include <stdint.h>

// ---------------- problem constants ----------------
namespace {
constexpr int T_  = 4096;
constexpr int D_  = 1024;
constexpr int E_  = 8;
constexpr int F_  = 2816;
constexpr int NP  = T_ * 2;       // 8192 (token,k) pairs
constexpr int N1  = 2 * F_;       // 5632
constexpr int BM  = 128;
constexpr int MAXTILES = 72;

// SMEM tile geometry: 128 rows x 32 k bf16, padded row stride 40 elems (80 B)
constexpr int ROWB   = 80;                 // bytes per smem row
constexpr int TILEB  = 128 * ROWB;         // 10240 bytes per (hi|lo) tile
// dyn smem layout: [AHI 2x][ALO 2x][BHI 2x][BLO 2x]
constexpr int AHI = 0;
constexpr int ALO = 2 * TILEB;             // 20480
constexpr int BHI = 4 * TILEB;             // 40960
constexpr int BLO = 6 * TILEB;             // 61440
constexpr int SMEM_DYN = 8 * TILEB;        // 81920
}

// ---------------- device scratch ----------------
__device__ float g_act[(size_t)NP * F_];      // silu(gate)*up
__device__ float g_pairout[(size_t)NP * D_];  // per-pair outputs

__device__ int g_cnt[E_];
__device__ int g_off[E_ + 1];
__device__ int g_pair_e[NP];
__device__ int g_pair_slot[NP];
__device__ int g_rowtok[NP];
__device__ int g_rowpair[NP];
__device__ int g_tile_e[MAXTILES];
__device__ int g_tile_r0[MAXTILES];
__device__ int g_tile_rows[MAXTILES];
__device__ int g_ntiles;

// ---------------- helpers ----------------
__device__ __forceinline__ uint32_t smem_u32(const void* p) {
    uint32_t a;
    asm("{ .reg .u64 t; cvta.to.shared.u64 t, %1; cvt.u32.u64 %0, t; }" : "=r"(a) : "l"(p));
    return a;
}
// pack 2 fp32 -> bf16x2 (e0 in low half)
__device__ __forceinline__ uint32_t pack_bf16(float e0, float e1) {
    uint32_t r;
    asm("cvt.rn.bf16x2.f32 %0, %1, %2;" : "=r"(r) : "f"(e1), "f"(e0));
    return r;
}
__device__ __forceinline__ void ldsm4(uint32_t& r0, uint32_t& r1, uint32_t& r2, uint32_t& r3,
                                      uint32_t addr) {
    asm volatile("ldmatrix.sync.aligned.m8n8.x4.shared.b16 {%0,%1,%2,%3}, [%4];"
                 : "=r"(r0), "=r"(r1), "=r"(r2), "=r"(r3) : "r"(addr));
}
__device__ __forceinline__ void mma16816(float* c, const uint32_t* a, uint32_t b0, uint32_t b1) {
    asm volatile(
        "mma.sync.aligned.m16n8k16.row.col.f32.bf16.bf16.f32 "
        "{%0,%1,%2,%3}, {%4,%5,%6,%7}, {%8,%9}, {%0,%1,%2,%3};"
        : "+f"(c[0]), "+f"(c[1]), "+f"(c[2]), "+f"(c[3])
        : "r"(a[0]), "r"(a[1]), "r"(a[2]), "r"(a[3]), "r"(b0), "r"(b1));
}
__device__ __forceinline__ void sts2(uint32_t addr, uint32_t v0, uint32_t v1) {
    asm volatile("st.shared.v2.b32 [%0], {%1, %2};" :: "r"(addr), "r"(v0), "r"(v1) : "memory");
}
// split float4 into bf16 hi/lo packed pairs
__device__ __forceinline__ void split4(float4 v, uint32_t& h0, uint32_t& h1,
                                       uint32_t& l0, uint32_t& l1) {
    h0 = pack_bf16(v.x, v.y);
    h1 = pack_bf16(v.z, v.w);
    float rx = v.x - __uint_as_float(h0 << 16);
    float ry = v.y - __uint_as_float(h0 & 0xffff0000u);
    float rz = v.z - __uint_as_float(h1 << 16);
    float rw = v.w - __uint_as_float(h1 & 0xffff0000u);
    l0 = pack_bf16(rx, ry);
    l1 = pack_bf16(rz, rw);
}

// ---------------- routing ----------------
__global__ void k_zero() { if (threadIdx.x < E_) g_cnt[threadIdx.x] = 0; }

__global__ void k_assign(const int* __restrict__ ids) {
    int p = blockIdx.x * 256 + threadIdx.x;
    if (p >= NP) return;
    int e = ids[p];
    e = e < 0 ? 0 : (e >= E_ ? E_ - 1 : e);
    g_pair_e[p] = e;
    g_pair_slot[p] = atomicAdd(&g_cnt[e], 1);
}

__global__ void k_tiles() {
    int off = 0;
    g_off[0] = 0;
    for (int e = 0; e < E_; e++) { off += g_cnt[e]; g_off[e + 1] = off; }
    int nt = 0;
    for (int e = 0; e < E_; e++)
        for (int r0 = g_off[e]; r0 < g_off[e + 1]; r0 += BM) {
            g_tile_e[nt] = e; g_tile_r0[nt] = r0;
            int rem = g_off[e + 1] - r0;
            g_tile_rows[nt] = rem < BM ? rem : BM;
            nt++;
        }
    g_ntiles = nt;
}

__global__ void k_rows() {
    int p = blockIdx.x * 256 + threadIdx.x;
    if (p >= NP) return;
    int gr = g_off[g_pair_e[p]] + g_pair_slot[p];
    g_rowtok[gr] = p >> 1;
    g_rowpair[gr] = p;
}

// ---------------- split-bf16 HMMA grouped GEMM ----------------
// G1: act[row, j] = silu(x_row . gup[e, j, :]) * (x_row . gup[e, F+j, :])
//     block covers 64 j-cols; B tile rows interleaved (2j = gate, 2j+1 = up)
// G2: pairout[pr, n] = act_row . down[e, n, :]   (N tile = 128)
template <bool G1>
__global__ void __launch_bounds__(256, 1)
moe_gemm_mma(const float* __restrict__ Aglob, const float* __restrict__ Bglob) {
    constexpr int KDIM = G1 ? D_ : F_;
    constexpr int NC   = KDIM / 32;

    const int bt = blockIdx.y;
    if (bt >= g_ntiles) return;

    const int e    = g_tile_e[bt];
    const int row0 = g_tile_r0[bt];
    const int rows = g_tile_rows[bt];
    const int bn0  = blockIdx.x * (G1 ? 64 : 128);   // j-cols (G1) or n-cols (G2)

    const float* __restrict__ A0 = G1 ? Aglob : (const float*)g_act;
    const float* __restrict__ Be = Bglob + (size_t)e * (G1 ? (size_t)N1 * D_ : (size_t)D_ * F_);

    extern __shared__ __align__(16) char dynraw[];
    const uint32_t dynbase = smem_u32(dynraw);

    __shared__ int s_map[BM];
    __shared__ int s_out[BM];

    const int tid  = threadIdx.x;
    const int wid  = tid >> 5;
    const int lane = tid & 31;

    if (tid < BM) {
        int amap = -1, omap = -1;
        if (tid < rows) {
            if (G1) { amap = g_rowtok[row0 + tid]; omap = row0 + tid; }
            else    { amap = row0 + tid;           omap = g_rowpair[row0 + tid]; }
        }
        s_map[tid] = amap; s_out[tid] = omap;
    }
    __syncthreads();

    // ---- chunk load to regs ----
    float4 pa[4], pb[4];
    auto loadchunk = [&](int c) {
        const int kofs = c * 32;
#pragma unroll
        for (int t = 0; t < 4; t++) {
            int idx = tid + t * 256;
            int row = idx >> 3, q = idx & 7;
            int ar = s_map[row];
            pa[t] = (ar >= 0) ? *(const float4*)(A0 + (size_t)ar * KDIM + kofs + q * 4)
                              : make_float4(0.f, 0.f, 0.f, 0.f);
        }
#pragma unroll
        for (int t = 0; t < 4; t++) {
            int idx = tid + t * 256;
            int row = idx >> 3, q = idx & 7;
            int brow;
            if (G1) { int j = row >> 1, s = row & 1; brow = bn0 + j + s * F_; }
            else    { brow = bn0 + row; }
            pb[t] = *(const float4*)(Be + (size_t)brow * KDIM + kofs + q * 4);
        }
    };
    auto stash = [&](int buf) {
        const uint32_t ah = dynbase + AHI + buf * TILEB;
        const uint32_t al = dynbase + ALO + buf * TILEB;
        const uint32_t bh = dynbase + BHI + buf * TILEB;
        const uint32_t bl = dynbase + BLO + buf * TILEB;
#pragma unroll
        for (int t = 0; t < 4; t++) {
            int idx = tid + t * 256;
            int row = idx >> 3, q = idx & 7;
            uint32_t off = (uint32_t)(row * ROWB + q * 8);
            uint32_t h0, h1, l0, l1;
            split4(pa[t], h0, h1, l0, l1);
            sts2(ah + off, h0, h1);
            sts2(al + off, l0, l1);
            split4(pb[t], h0, h1, l0, l1);
            sts2(bh + off, h0, h1);
            sts2(bl + off, l0, l1);
        }
    };

    // warp tile: 64 m x 32 n
    const int wm = (wid >> 2) * 64;
    const int wn = (wid & 3) * 32;
    const int lrow  = lane & 15;
    const int lcol8 = (lane >> 4) * 8;

    float acc[4][4][4];
#pragma unroll
    for (int i = 0; i < 4; i++)
#pragma unroll
        for (int j = 0; j < 4; j++)
#pragma unroll
            for (int k = 0; k < 4; k++) acc[i][j][k] = 0.f;

    loadchunk(0);
    stash(0);
    __syncthreads();

    for (int c = 0; c < NC; c++) {
        const int buf = c & 1;
        if (c + 1 < NC) loadchunk(c + 1);

        const uint32_t ah = dynbase + AHI + buf * TILEB;
        const uint32_t al = dynbase + ALO + buf * TILEB;
        const uint32_t bh = dynbase + BHI + buf * TILEB;
        const uint32_t bl = dynbase + BLO + buf * TILEB;

#pragma unroll
        for (int kk = 0; kk < 2; kk++) {
            const uint32_t koffB = (uint32_t)((kk * 16 + lcol8) * 2);
            // B frags: 2 n16 groups x (hi,lo)
            uint32_t bfh[2][4], bfl[2][4];
#pragma unroll
            for (int g = 0; g < 2; g++) {
                uint32_t roff = (uint32_t)((wn + g * 16 + lrow) * ROWB) + koffB;
                ldsm4(bfh[g][0], bfh[g][1], bfh[g][2], bfh[g][3], bh + roff);
                ldsm4(bfl[g][0], bfl[g][1], bfl[g][2], bfl[g][3], bl + roff);
            }
#pragma unroll
            for (int mi = 0; mi < 4; mi++) {
                uint32_t roff = (uint32_t)((wm + mi * 16 + lrow) * ROWB) + koffB;
                uint32_t afh[4], afl[4];
                ldsm4(afh[0], afh[1], afh[2], afh[3], ah + roff);
                ldsm4(afl[0], afl[1], afl[2], afl[3], al + roff);
#pragma unroll
                for (int ni = 0; ni < 4; ni++) {
                    const int g = ni >> 1, sub = ni & 1;
                    uint32_t b0h = bfh[g][sub], b1h = bfh[g][sub + 2];
                    uint32_t b0l = bfl[g][sub], b1l = bfl[g][sub + 2];
                    mma16816(acc[mi][ni], afh, b0h, b1h);
                    mma16816(acc[mi][ni], afh, b0l, b1l);
                    mma16816(acc[mi][ni], afl, b0h, b1h);
                }
            }
        }
        if (c + 1 < NC) {
            __syncthreads();
            stash((c + 1) & 1);
            __syncthreads();
        }
    }

    __syncthreads();   // all MMAs done; smem reusable for epilogue staging
    float* stg = (float*)dynraw;
    const int group = lane >> 2;
    const int tig   = lane & 3;

    if (G1) {
        // acc (c0,c1) = (gate, up) of j; (c2,c3) same at m+8. Stage act[128][68].
#pragma unroll
        for (int mi = 0; mi < 4; mi++) {
            int m = wm + mi * 16 + group;
#pragma unroll
            for (int ni = 0; ni < 4; ni++) {
                int j = (wid & 3) * 16 + ni * 4 + tig;
                float g0 = acc[mi][ni][0], u0 = acc[mi][ni][1];
                float g1 = acc[mi][ni][2], u1 = acc[mi][ni][3];
                stg[m * 68 + j]       = g0 / (1.f + __expf(-g0)) * u0;
                stg[(m + 8) * 68 + j] = g1 / (1.f + __expf(-g1)) * u1;
            }
        }
        __syncthreads();
#pragma unroll
        for (int t = 0; t < 8; t++) {
            int idx = tid + t * 256;
            int row = idx >> 4, q = idx & 15;
            int orow = s_out[row];
            if (orow >= 0)
                *(float4*)((float*)g_act + (size_t)orow * F_ + bn0 + q * 4) =
                    *(const float4*)(stg + row * 68 + q * 4);
        }
    } else {
        // Stage C[128][132]
#pragma unroll
        for (int mi = 0; mi < 4; mi++) {
            int m = wm + mi * 16 + group;
#pragma unroll
            for (int ni = 0; ni < 4; ni++) {
                int n = wn + ni * 8 + tig * 2;
                *(float2*)(stg + m * 132 + n)       = make_float2(acc[mi][ni][0], acc[mi][ni][1]);
                *(float2*)(stg + (m + 8) * 132 + n) = make_float2(acc[mi][ni][2], acc[mi][ni][3]);
            }
        }
        __syncthreads();
#pragma unroll
        for (int t = 0; t < 16; t++) {
            int idx = tid + t * 256;
            int row = idx >> 5, q = idx & 31;
            int orow = s_out[row];
            if (orow >= 0)
                *(float4*)((float*)g_pairout + (size_t)orow * D_ + bn0 + q * 4) =
                    *(const float4*)(stg + row * 132 + q * 4);
        }
    }
}

// ---------------- weighted combine ----------------
__global__ void k_combine(const float* __restrict__ tw, float* __restrict__ out) {
    int d = blockIdx.x * 256 + threadIdx.x;
    int t = blockIdx.y;
    float w0 = tw[t * 2 + 0];
    float w1 = tw[t * 2 + 1];
    out[(size_t)t * D_ + d] =
        w0 * g_pairout[(size_t)(2 * t + 0) * D_ + d] +
        w1 * g_pairout[(size_t)(2 * t + 1) * D_ + d];
}

// ---------------- launch ----------------
extern "C" void kernel_launch(void* const* d_in, const int* in_sizes, int n_in,
                              void* d_out, int out_size) {
    const float* x   = (const float*)d_in[0];
    const float* gup = (const float*)d_in[1];
    const float* dwn = (const float*)d_in[2];
    const float* tw  = (const float*)d_in[3];
    const int*   ids = (const int*)d_in[4];
    float* out = (float*)d_out;

    cudaFuncSetAttribute(moe_gemm_mma<true>,  cudaFuncAttributeMaxDynamicSharedMemorySize, SMEM_DYN);
    cudaFuncSetAttribute(moe_gemm_mma<false>, cudaFuncAttributeMaxDynamicSharedMemorySize, SMEM_DYN);

    k_zero<<<1, 32>>>();
    k_assign<<<NP / 256, 256>>>(ids);
    k_tiles<<<1, 1>>>();
    k_rows<<<NP / 256, 256>>>();

    moe_gemm_mma<true ><<<dim3(F_ / 64, MAXTILES), 256, SMEM_DYN>>>(x, gup);
    moe_gemm_mma<false><<<dim3(D_ / 128, MAXTILES), 256, SMEM_DYN>>>(nullptr, dwn);

    k_combine<<<dim3(D_ / 256, T_), 256>>>(tw, out);
}

// round 4
// speedup vs baseline: 2.3536x; 1.1291x over previous
#include <cuda_runtime.h>
#include <cuda_bf16.h>
#include <stdint.h>

// ---------------- problem constants ----------------
namespace {
constexpr int T_  = 4096;
constexpr int D_  = 1024;
constexpr int E_  = 8;
constexpr int F_  = 2816;
constexpr int NP  = T_ * 2;       // 8192 (token,k) pairs
constexpr int N1  = 2 * F_;       // 5632
constexpr int BM  = 128;
constexpr int MAXTILES = 72;

// smem: per k32-chunk buffer, 4 planes (Ah, Al, Bh, Bl) of 128x32 bf16 = 8KB
constexpr int PL   = 8192;
constexpr int BUF  = 4 * PL;          // 32768 per buffer
constexpr int SMEM_DYN = 69632;       // max(2*BUF, G2 staging 128*132*4=67584)
}

// ---------------- device scratch (static, allocation-free) ----------------
__device__ __align__(16) __nv_bfloat16 g_x_hi[(size_t)T_ * D_];
__device__ __align__(16) __nv_bfloat16 g_x_lo[(size_t)T_ * D_];
__device__ __align__(16) __nv_bfloat16 g_gup_hi[(size_t)E_ * N1 * D_];
__device__ __align__(16) __nv_bfloat16 g_gup_lo[(size_t)E_ * N1 * D_];
__device__ __align__(16) __nv_bfloat16 g_dwn_hi[(size_t)E_ * D_ * F_];
__device__ __align__(16) __nv_bfloat16 g_dwn_lo[(size_t)E_ * D_ * F_];
__device__ __align__(16) __nv_bfloat16 g_act_hi[(size_t)NP * F_];
__device__ __align__(16) __nv_bfloat16 g_act_lo[(size_t)NP * F_];
__device__ float g_pairout[(size_t)NP * D_];

__device__ int g_cnt[E_];
__device__ int g_off[E_ + 1];
__device__ int g_pair_e[NP];
__device__ int g_pair_slot[NP];
__device__ int g_rowtok[NP];
__device__ int g_rowpair[NP];
__device__ int g_tile_e[MAXTILES];
__device__ int g_tile_r0[MAXTILES];
__device__ int g_tile_rows[MAXTILES];
__device__ int g_ntiles;

// ---------------- helpers ----------------
__device__ __forceinline__ uint32_t smem_u32(const void* p) {
    uint32_t a;
    asm("{ .reg .u64 t; cvta.to.shared.u64 t, %1; cvt.u32.u64 %0, t; }" : "=r"(a) : "l"(p));
    return a;
}
__device__ __forceinline__ uint32_t pack_bf16(float e0, float e1) {
    uint32_t r;
    asm("cvt.rn.bf16x2.f32 %0, %1, %2;" : "=r"(r) : "f"(e1), "f"(e0));
    return r;
}
__device__ __forceinline__ void split4(float4 v, uint32_t& h0, uint32_t& h1,
                                       uint32_t& l0, uint32_t& l1) {
    h0 = pack_bf16(v.x, v.y);
    h1 = pack_bf16(v.z, v.w);
    float rx = v.x - __uint_as_float(h0 << 16);
    float ry = v.y - __uint_as_float(h0 & 0xffff0000u);
    float rz = v.z - __uint_as_float(h1 << 16);
    float rw = v.w - __uint_as_float(h1 & 0xffff0000u);
    l0 = pack_bf16(rx, ry);
    l1 = pack_bf16(rz, rw);
}
__device__ __forceinline__ void ldsm4(uint32_t& r0, uint32_t& r1, uint32_t& r2, uint32_t& r3,
                                      uint32_t addr) {
    asm volatile("ldmatrix.sync.aligned.m8n8.x4.shared.b16 {%0,%1,%2,%3}, [%4];"
                 : "=r"(r0), "=r"(r1), "=r"(r2), "=r"(r3) : "r"(addr));
}
__device__ __forceinline__ void mma16816(float* c, const uint32_t* a, uint32_t b0, uint32_t b1) {
    asm volatile(
        "mma.sync.aligned.m16n8k16.row.col.f32.bf16.bf16.f32 "
        "{%0,%1,%2,%3}, {%4,%5,%6,%7}, {%8,%9}, {%0,%1,%2,%3};"
        : "+f"(c[0]), "+f"(c[1]), "+f"(c[2]), "+f"(c[3])
        : "r"(a[0]), "r"(a[1]), "r"(a[2]), "r"(a[3]), "r"(b0), "r"(b1));
}
__device__ __forceinline__ void cp_async16(uint32_t dst, const void* src, int sz) {
    asm volatile("cp.async.cg.shared.global [%0], [%1], 16, %2;"
                 :: "r"(dst), "l"(src), "r"(sz) : "memory");
}
__device__ __forceinline__ void cp_commit() {
    asm volatile("cp.async.commit_group;" ::: "memory");
}
__device__ __forceinline__ void cp_wait0() {
    asm volatile("cp.async.wait_group 0;" ::: "memory");
}
__device__ __forceinline__ void cp_wait1() {
    asm volatile("cp.async.wait_group 1;" ::: "memory");
}

// ---------------- routing ----------------
__global__ void k_zero() { if (threadIdx.x < E_) g_cnt[threadIdx.x] = 0; }

__global__ void k_assign(const int* __restrict__ ids) {
    int p = blockIdx.x * 256 + threadIdx.x;
    if (p >= NP) return;
    int e = ids[p];
    e = e < 0 ? 0 : (e >= E_ ? E_ - 1 : e);
    g_pair_e[p] = e;
    g_pair_slot[p] = atomicAdd(&g_cnt[e], 1);
}

__global__ void k_tiles() {
    int off = 0;
    g_off[0] = 0;
    for (int e = 0; e < E_; e++) { off += g_cnt[e]; g_off[e + 1] = off; }
    int nt = 0;
    for (int e = 0; e < E_; e++)
        for (int r0 = g_off[e]; r0 < g_off[e + 1]; r0 += BM) {
            g_tile_e[nt] = e; g_tile_r0[nt] = r0;
            int rem = g_off[e + 1] - r0;
            g_tile_rows[nt] = rem < BM ? rem : BM;
            nt++;
        }
    g_ntiles = nt;
}

__global__ void k_rows() {
    int p = blockIdx.x * 256 + threadIdx.x;
    if (p >= NP) return;
    int gr = g_off[g_pair_e[p]] + g_pair_slot[p];
    g_rowtok[gr] = p >> 1;
    g_rowpair[gr] = p;
}

// ---------------- fp32 -> bf16 hi/lo pre-split ----------------
__global__ void k_split(const float4* __restrict__ src, uint2* __restrict__ hi,
                        uint2* __restrict__ lo, int n4) {
    int i = blockIdx.x * 256 + threadIdx.x;
    if (i >= n4) return;
    float4 v = src[i];
    uint32_t h0, h1, l0, l1;
    split4(v, h0, h1, l0, l1);
    hi[i] = make_uint2(h0, h1);
    lo[i] = make_uint2(l0, l1);
}

// ---------------- split-bf16 HMMA grouped GEMM (cp.async feed) ----------------
// G1: act[row, j] = silu(x_row . gup[e, j, :]) * (x_row . gup[e, F+j, :])
//     block covers 64 j; B rows interleaved (2j = gate, 2j+1 = up)  KDIM=1024
// G2: pairout[pr, n] = act_row . down[e, n, :]  (N tile 128)        KDIM=2816
template <bool G1>
__global__ void __launch_bounds__(256, 2)
moe_gemm_mma() {
    constexpr int KDIM = G1 ? D_ : F_;
    constexpr int NC   = KDIM / 32;

    const int bt = blockIdx.y;
    if (bt >= g_ntiles) return;

    const int e    = g_tile_e[bt];
    const int row0 = g_tile_r0[bt];
    const int rows = g_tile_rows[bt];
    const int bn0  = blockIdx.x * (G1 ? 64 : 128);

    const __nv_bfloat16* __restrict__ Ah = G1 ? g_x_hi : g_act_hi;
    const __nv_bfloat16* __restrict__ Al = G1 ? g_x_lo : g_act_lo;
    const size_t eoff = (size_t)e * (G1 ? (size_t)N1 * D_ : (size_t)D_ * F_);
    const __nv_bfloat16* __restrict__ Bh = (G1 ? g_gup_hi : g_dwn_hi) + eoff;
    const __nv_bfloat16* __restrict__ Bl = (G1 ? g_gup_lo : g_dwn_lo) + eoff;

    extern __shared__ __align__(16) char dynraw[];
    const uint32_t dynbase = smem_u32(dynraw);

    __shared__ int s_map[BM];
    __shared__ int s_out[BM];

    const int tid  = threadIdx.x;
    const int wid  = tid >> 5;
    const int lane = tid & 31;

    if (tid < BM) {
        int amap = -1, omap = -1;
        if (tid < rows) {
            if (G1) { amap = g_rowtok[row0 + tid]; omap = row0 + tid; }
            else    { amap = row0 + tid;           omap = g_rowpair[row0 + tid]; }
        }
        s_map[tid] = amap; s_out[tid] = omap;
    }
    __syncthreads();

    // per-thread cp.async assignments (2 units A, 2 units B)
    const int rA0 = tid >> 2,              qA0 = tid & 3;
    const int rA1 = (tid + 256) >> 2,      qA1 = tid & 3;

    auto issue = [&](int c) {
        const uint32_t base = dynbase + (c & 1) * BUF;
        const int kofs = c * 32;
        // A planes
        {
            int ar = s_map[rA0];
            int sz = ar >= 0 ? 16 : 0;
            size_t so = ((size_t)(ar < 0 ? 0 : ar) * KDIM + kofs) * 2 + qA0 * 16;
            uint32_t doff = rA0 * 64 + (((uint32_t)(qA0 ^ (rA0 & 3))) << 4);
            cp_async16(base + doff,      (const char*)Ah + so, sz);
            cp_async16(base + PL + doff, (const char*)Al + so, sz);
        }
        {
            int ar = s_map[rA1];
            int sz = ar >= 0 ? 16 : 0;
            size_t so = ((size_t)(ar < 0 ? 0 : ar) * KDIM + kofs) * 2 + qA1 * 16;
            uint32_t doff = rA1 * 64 + (((uint32_t)(qA1 ^ (rA1 & 3))) << 4);
            cp_async16(base + doff,      (const char*)Ah + so, sz);
            cp_async16(base + PL + doff, (const char*)Al + so, sz);
        }
        // B planes
#pragma unroll
        for (int t = 0; t < 2; t++) {
            int idx = tid + t * 256;
            int row = idx >> 2, q = idx & 3;
            int brow = G1 ? (bn0 + (row >> 1) + (row & 1) * F_) : (bn0 + row);
            size_t so = ((size_t)brow * KDIM + kofs) * 2 + q * 16;
            uint32_t doff = row * 64 + (((uint32_t)(q ^ (row & 3))) << 4);
            cp_async16(base + 2 * PL + doff, (const char*)Bh + so, 16);
            cp_async16(base + 3 * PL + doff, (const char*)Bl + so, 16);
        }
        cp_commit();
    };

    // warp tile: 64 m x 32 n
    const int wm = (wid >> 2) * 64;
    const int wn = (wid & 3) * 32;
    const int lrow  = lane & 15;
    const int qhalf = lane >> 4;     // 0/1 -> 16B half within k32

    float acc[4][4][4];
#pragma unroll
    for (int i = 0; i < 4; i++)
#pragma unroll
        for (int j = 0; j < 4; j++)
#pragma unroll
            for (int k = 0; k < 4; k++) acc[i][j][k] = 0.f;

    issue(0);

    for (int c = 0; c < NC; c++) {
        if (c + 1 < NC) { issue(c + 1); cp_wait1(); }
        else            { cp_wait0(); }
        __syncthreads();

        const uint32_t base = dynbase + (c & 1) * BUF;
        const uint32_t ah = base, al = base + PL, bh = base + 2 * PL, bl = base + 3 * PL;

#pragma unroll
        for (int kk = 0; kk < 2; kk++) {
            const int qlog = kk * 2 + qhalf;
            uint32_t bfh[2][4], bfl[2][4];
#pragma unroll
            for (int g = 0; g < 2; g++) {
                int r = wn + g * 16 + lrow;
                uint32_t ao = (uint32_t)(r * 64 + ((qlog ^ (r & 3)) << 4));
                ldsm4(bfh[g][0], bfh[g][1], bfh[g][2], bfh[g][3], bh + ao);
                ldsm4(bfl[g][0], bfl[g][1], bfl[g][2], bfl[g][3], bl + ao);
            }
#pragma unroll
            for (int mi = 0; mi < 4; mi++) {
                int r = wm + mi * 16 + lrow;
                uint32_t ao = (uint32_t)(r * 64 + ((qlog ^ (r & 3)) << 4));
                uint32_t afh[4], afl[4];
                ldsm4(afh[0], afh[1], afh[2], afh[3], ah + ao);
                ldsm4(afl[0], afl[1], afl[2], afl[3], al + ao);
#pragma unroll
                for (int ni = 0; ni < 4; ni++) {
                    const int g = ni >> 1, sub = ni & 1;
                    mma16816(acc[mi][ni], afh, bfh[g][sub], bfh[g][sub + 2]);
                    mma16816(acc[mi][ni], afh, bfl[g][sub], bfl[g][sub + 2]);
                    mma16816(acc[mi][ni], afl, bfh[g][sub], bfh[g][sub + 2]);
                }
            }
        }
        __syncthreads();
    }

    // ---- epilogue (smem reused for staging) ----
    float* stg = (float*)dynraw;
    const int group = lane >> 2;
    const int tig   = lane & 3;

    if (G1) {
#pragma unroll
        for (int mi = 0; mi < 4; mi++) {
            int m = wm + mi * 16 + group;
#pragma unroll
            for (int ni = 0; ni < 4; ni++) {
                int j = (wid & 3) * 16 + ni * 4 + tig;
                float g0 = acc[mi][ni][0], u0 = acc[mi][ni][1];
                float g1 = acc[mi][ni][2], u1 = acc[mi][ni][3];
                stg[m * 68 + j]       = g0 / (1.f + __expf(-g0)) * u0;
                stg[(m + 8) * 68 + j] = g1 / (1.f + __expf(-g1)) * u1;
            }
        }
        __syncthreads();
#pragma unroll
        for (int t = 0; t < 8; t++) {
            int idx = tid + t * 256;
            int row = idx >> 4, q = idx & 15;
            int orow = s_out[row];
            if (orow >= 0) {
                float4 v = *(const float4*)(stg + row * 68 + q * 4);
                uint32_t h0, h1, l0, l1;
                split4(v, h0, h1, l0, l1);
                size_t ob = ((size_t)orow * F_ + bn0 + q * 4) * 2;
                *(uint2*)((char*)g_act_hi + ob) = make_uint2(h0, h1);
                *(uint2*)((char*)g_act_lo + ob) = make_uint2(l0, l1);
            }
        }
    } else {
#pragma unroll
        for (int mi = 0; mi < 4; mi++) {
            int m = wm + mi * 16 + group;
#pragma unroll
            for (int ni = 0; ni < 4; ni++) {
                int n = wn + ni * 8 + tig * 2;
                *(float2*)(stg + m * 132 + n)       = make_float2(acc[mi][ni][0], acc[mi][ni][1]);
                *(float2*)(stg + (m + 8) * 132 + n) = make_float2(acc[mi][ni][2], acc[mi][ni][3]);
            }
        }
        __syncthreads();
#pragma unroll
        for (int t = 0; t < 16; t++) {
            int idx = tid + t * 256;
            int row = idx >> 5, q = idx & 31;
            int orow = s_out[row];
            if (orow >= 0)
                *(float4*)(g_pairout + (size_t)orow * D_ + bn0 + q * 4) =
                    *(const float4*)(stg + row * 132 + q * 4);
        }
    }
}

// ---------------- weighted combine ----------------
__global__ void k_combine(const float* __restrict__ tw, float* __restrict__ out) {
    int d = blockIdx.x * 256 + threadIdx.x;
    int t = blockIdx.y;
    float w0 = tw[t * 2 + 0];
    float w1 = tw[t * 2 + 1];
    out[(size_t)t * D_ + d] =
        w0 * g_pairout[(size_t)(2 * t + 0) * D_ + d] +
        w1 * g_pairout[(size_t)(2 * t + 1) * D_ + d];
}

// ---------------- launch ----------------
extern "C" void kernel_launch(void* const* d_in, const int* in_sizes, int n_in,
                              void* d_out, int out_size) {
    const float* x   = (const float*)d_in[0];
    const float* gup = (const float*)d_in[1];
    const float* dwn = (const float*)d_in[2];
    const float* tw  = (const float*)d_in[3];
    const int*   ids = (const int*)d_in[4];
    float* out = (float*)d_out;

    cudaFuncSetAttribute(moe_gemm_mma<true>,  cudaFuncAttributeMaxDynamicSharedMemorySize, SMEM_DYN);
    cudaFuncSetAttribute(moe_gemm_mma<false>, cudaFuncAttributeMaxDynamicSharedMemorySize, SMEM_DYN);

    void *xh, *xl, *gh, *gl, *dh, *dl;
    cudaGetSymbolAddress(&xh, g_x_hi);   cudaGetSymbolAddress(&xl, g_x_lo);
    cudaGetSymbolAddress(&gh, g_gup_hi); cudaGetSymbolAddress(&gl, g_gup_lo);
    cudaGetSymbolAddress(&dh, g_dwn_hi); cudaGetSymbolAddress(&dl, g_dwn_lo);

    k_zero<<<1, 32>>>();
    k_assign<<<NP / 256, 256>>>(ids);
    k_tiles<<<1, 1>>>();
    k_rows<<<NP / 256, 256>>>();

    {
        int n4 = T_ * D_ / 4;
        k_split<<<(n4 + 255) / 256, 256>>>((const float4*)x, (uint2*)xh, (uint2*)xl, n4);
    }
    {
        int n4 = (int)((size_t)E_ * N1 * D_ / 4);
        k_split<<<(n4 + 255) / 256, 256>>>((const float4*)gup, (uint2*)gh, (uint2*)gl, n4);
    }
    {
        int n4 = (int)((size_t)E_ * D_ * F_ / 4);
        k_split<<<(n4 + 255) / 256, 256>>>((const float4*)dwn, (uint2*)dh, (uint2*)dl, n4);
    }

    moe_gemm_mma<true ><<<dim3(F_ / 64, MAXTILES), 256, SMEM_DYN>>>();
    moe_gemm_mma<false><<<dim3(D_ / 128, MAXTILES), 256, SMEM_DYN>>>();

    k_combine<<<dim3(D_ / 256, T_), 256>>>(tw, out);
}

// round 5
// speedup vs baseline: 2.4901x; 1.0580x over previous
#include <cuda_runtime.h>
#include <cuda_bf16.h>
#include <stdint.h>

// ---------------- problem constants ----------------
namespace {
constexpr int T_  = 4096;
constexpr int D_  = 1024;
constexpr int E_  = 8;
constexpr int F_  = 2816;
constexpr int NP  = T_ * 2;       // 8192 (token,k) pairs
constexpr int N1  = 2 * F_;       // 5632
constexpr int BM  = 128;
constexpr int MAXTILES = 72;

// smem: per k32-chunk buffer, 4 planes (Ah, Al, Bh, Bl) of 128x32 bf16 = 8KB
constexpr int PL   = 8192;
constexpr int BUF  = 4 * PL;          // 32768 per buffer
constexpr int NBUF = 3;
constexpr int SMEM_DYN = NBUF * BUF;  // 98304 (>= G2 staging 128*132*4 = 67584)
}

// ---------------- device scratch (static, allocation-free) ----------------
__device__ __align__(16) __nv_bfloat16 g_x_hi[(size_t)T_ * D_];
__device__ __align__(16) __nv_bfloat16 g_x_lo[(size_t)T_ * D_];
__device__ __align__(16) __nv_bfloat16 g_gup_hi[(size_t)E_ * N1 * D_];
__device__ __align__(16) __nv_bfloat16 g_gup_lo[(size_t)E_ * N1 * D_];
__device__ __align__(16) __nv_bfloat16 g_dwn_hi[(size_t)E_ * D_ * F_];
__device__ __align__(16) __nv_bfloat16 g_dwn_lo[(size_t)E_ * D_ * F_];
__device__ __align__(16) __nv_bfloat16 g_act_hi[(size_t)NP * F_];
__device__ __align__(16) __nv_bfloat16 g_act_lo[(size_t)NP * F_];
__device__ float g_pairout[(size_t)NP * D_];

__device__ int g_cnt[E_];
__device__ int g_off[E_ + 1];
__device__ int g_pair_e[NP];
__device__ int g_pair_slot[NP];
__device__ int g_rowtok[NP];
__device__ int g_rowpair[NP];
__device__ int g_tile_e[MAXTILES];
__device__ int g_tile_r0[MAXTILES];
__device__ int g_tile_rows[MAXTILES];
__device__ int g_ntiles;

// ---------------- helpers ----------------
__device__ __forceinline__ uint32_t smem_u32(const void* p) {
    uint32_t a;
    asm("{ .reg .u64 t; cvta.to.shared.u64 t, %1; cvt.u32.u64 %0, t; }" : "=r"(a) : "l"(p));
    return a;
}
__device__ __forceinline__ uint32_t pack_bf16(float e0, float e1) {
    uint32_t r;
    asm("cvt.rn.bf16x2.f32 %0, %1, %2;" : "=r"(r) : "f"(e1), "f"(e0));
    return r;
}
__device__ __forceinline__ void split4(float4 v, uint32_t& h0, uint32_t& h1,
                                       uint32_t& l0, uint32_t& l1) {
    h0 = pack_bf16(v.x, v.y);
    h1 = pack_bf16(v.z, v.w);
    float rx = v.x - __uint_as_float(h0 << 16);
    float ry = v.y - __uint_as_float(h0 & 0xffff0000u);
    float rz = v.z - __uint_as_float(h1 << 16);
    float rw = v.w - __uint_as_float(h1 & 0xffff0000u);
    l0 = pack_bf16(rx, ry);
    l1 = pack_bf16(rz, rw);
}
__device__ __forceinline__ void ldsm4(uint32_t& r0, uint32_t& r1, uint32_t& r2, uint32_t& r3,
                                      uint32_t addr) {
    asm volatile("ldmatrix.sync.aligned.m8n8.x4.shared.b16 {%0,%1,%2,%3}, [%4];"
                 : "=r"(r0), "=r"(r1), "=r"(r2), "=r"(r3) : "r"(addr));
}
__device__ __forceinline__ void mma16816(float* c, const uint32_t* a, uint32_t b0, uint32_t b1) {
    asm volatile(
        "mma.sync.aligned.m16n8k16.row.col.f32.bf16.bf16.f32 "
        "{%0,%1,%2,%3}, {%4,%5,%6,%7}, {%8,%9}, {%0,%1,%2,%3};"
        : "+f"(c[0]), "+f"(c[1]), "+f"(c[2]), "+f"(c[3])
        : "r"(a[0]), "r"(a[1]), "r"(a[2]), "r"(a[3]), "r"(b0), "r"(b1));
}
__device__ __forceinline__ void cp_async16(uint32_t dst, const void* src, int sz) {
    asm volatile("cp.async.cg.shared.global [%0], [%1], 16, %2;"
                 :: "r"(dst), "l"(src), "r"(sz) : "memory");
}
__device__ __forceinline__ void cp_commit() {
    asm volatile("cp.async.commit_group;" ::: "memory");
}
__device__ __forceinline__ void cp_wait0() {
    asm volatile("cp.async.wait_group 0;" ::: "memory");
}
__device__ __forceinline__ void cp_wait1() {
    asm volatile("cp.async.wait_group 1;" ::: "memory");
}

// ---------------- routing ----------------
__global__ void k_zero() { if (threadIdx.x < E_) g_cnt[threadIdx.x] = 0; }

__global__ void k_assign(const int* __restrict__ ids) {
    int p = blockIdx.x * 256 + threadIdx.x;
    if (p >= NP) return;
    int e = ids[p];
    e = e < 0 ? 0 : (e >= E_ ? E_ - 1 : e);
    g_pair_e[p] = e;
    g_pair_slot[p] = atomicAdd(&g_cnt[e], 1);
}

__global__ void k_tiles() {
    int off = 0;
    g_off[0] = 0;
    for (int e = 0; e < E_; e++) { off += g_cnt[e]; g_off[e + 1] = off; }
    int nt = 0;
    for (int e = 0; e < E_; e++)
        for (int r0 = g_off[e]; r0 < g_off[e + 1]; r0 += BM) {
            g_tile_e[nt] = e; g_tile_r0[nt] = r0;
            int rem = g_off[e + 1] - r0;
            g_tile_rows[nt] = rem < BM ? rem : BM;
            nt++;
        }
    g_ntiles = nt;
}

__global__ void k_rows() {
    int p = blockIdx.x * 256 + threadIdx.x;
    if (p >= NP) return;
    int gr = g_off[g_pair_e[p]] + g_pair_slot[p];
    g_rowtok[gr] = p >> 1;
    g_rowpair[gr] = p;
}

// ---------------- fp32 -> bf16 hi/lo pre-split ----------------
__global__ void k_split(const float4* __restrict__ src, uint2* __restrict__ hi,
                        uint2* __restrict__ lo, int n4) {
    int i = blockIdx.x * 256 + threadIdx.x;
    if (i >= n4) return;
    float4 v = src[i];
    uint32_t h0, h1, l0, l1;
    split4(v, h0, h1, l0, l1);
    hi[i] = make_uint2(h0, h1);
    lo[i] = make_uint2(l0, l1);
}

// ---------------- split-bf16 HMMA grouped GEMM (3-stage cp.async) ----------------
// G1: act[row, j] = silu(x_row . gup[e, j, :]) * (x_row . gup[e, F+j, :])
//     block covers 64 j; B rows interleaved (2j = gate, 2j+1 = up)  KDIM=1024
// G2: pairout[pr, n] = act_row . down[e, n, :]  (N tile 128)        KDIM=2816
template <bool G1>
__global__ void __launch_bounds__(256, 2)
moe_gemm_mma() {
    constexpr int KDIM = G1 ? D_ : F_;
    constexpr int NC   = KDIM / 32;

    const int bt = blockIdx.y;
    if (bt >= g_ntiles) return;

    const int e    = g_tile_e[bt];
    const int row0 = g_tile_r0[bt];
    const int rows = g_tile_rows[bt];
    const int bn0  = blockIdx.x * (G1 ? 64 : 128);

    const __nv_bfloat16* __restrict__ Ah = G1 ? g_x_hi : g_act_hi;
    const __nv_bfloat16* __restrict__ Al = G1 ? g_x_lo : g_act_lo;
    const size_t eoff = (size_t)e * (G1 ? (size_t)N1 * D_ : (size_t)D_ * F_);
    const __nv_bfloat16* __restrict__ Bh = (G1 ? g_gup_hi : g_dwn_hi) + eoff;
    const __nv_bfloat16* __restrict__ Bl = (G1 ? g_gup_lo : g_dwn_lo) + eoff;

    extern __shared__ __align__(16) char dynraw[];
    const uint32_t dynbase = smem_u32(dynraw);

    __shared__ int s_map[BM];
    __shared__ int s_out[BM];

    const int tid  = threadIdx.x;
    const int wid  = tid >> 5;
    const int lane = tid & 31;

    if (tid < BM) {
        int amap = -1, omap = -1;
        if (tid < rows) {
            if (G1) { amap = g_rowtok[row0 + tid]; omap = row0 + tid; }
            else    { amap = row0 + tid;           omap = g_rowpair[row0 + tid]; }
        }
        s_map[tid] = amap; s_out[tid] = omap;
    }
    __syncthreads();

    // per-thread cp.async assignments (2 units A, 2 units B)
    const int rA0 = tid >> 2,         qA0 = tid & 3;
    const int rA1 = (tid + 256) >> 2, qA1 = tid & 3;

    auto issue = [&](int c) {
        const uint32_t base = dynbase + (uint32_t)(c % NBUF) * BUF;
        const int kofs = c * 32;
        {
            int ar = s_map[rA0];
            int sz = ar >= 0 ? 16 : 0;
            size_t so = ((size_t)(ar < 0 ? 0 : ar) * KDIM + kofs) * 2 + qA0 * 16;
            uint32_t doff = rA0 * 64 + (((uint32_t)(qA0 ^ (rA0 & 3))) << 4);
            cp_async16(base + doff,      (const char*)Ah + so, sz);
            cp_async16(base + PL + doff, (const char*)Al + so, sz);
        }
        {
            int ar = s_map[rA1];
            int sz = ar >= 0 ? 16 : 0;
            size_t so = ((size_t)(ar < 0 ? 0 : ar) * KDIM + kofs) * 2 + qA1 * 16;
            uint32_t doff = rA1 * 64 + (((uint32_t)(qA1 ^ (rA1 & 3))) << 4);
            cp_async16(base + doff,      (const char*)Ah + so, sz);
            cp_async16(base + PL + doff, (const char*)Al + so, sz);
        }
#pragma unroll
        for (int t = 0; t < 2; t++) {
            int idx = tid + t * 256;
            int row = idx >> 2, q = idx & 3;
            int brow = G1 ? (bn0 + (row >> 1) + (row & 1) * F_) : (bn0 + row);
            size_t so = ((size_t)brow * KDIM + kofs) * 2 + q * 16;
            uint32_t doff = row * 64 + (((uint32_t)(q ^ (row & 3))) << 4);
            cp_async16(base + 2 * PL + doff, (const char*)Bh + so, 16);
            cp_async16(base + 3 * PL + doff, (const char*)Bl + so, 16);
        }
        cp_commit();
    };

    // warp tile: 64 m x 32 n
    const int wm = (wid >> 2) * 64;
    const int wn = (wid & 3) * 32;
    const int lrow  = lane & 15;
    const int qhalf = lane >> 4;     // 0/1 -> 16B half within k32

    float acc[4][4][4];
#pragma unroll
    for (int i = 0; i < 4; i++)
#pragma unroll
        for (int j = 0; j < 4; j++)
#pragma unroll
            for (int k = 0; k < 4; k++) acc[i][j][k] = 0.f;

    issue(0);
    if (NC > 1) issue(1);

    for (int c = 0; c < NC; c++) {
        if (c + 1 < NC) cp_wait1();
        else            cp_wait0();
        __syncthreads();   // stage c visible to all; all warps done computing c-1

        const uint32_t base = dynbase + (uint32_t)(c % NBUF) * BUF;
        const uint32_t ah = base, al = base + PL, bh = base + 2 * PL, bl = base + 3 * PL;

#pragma unroll
        for (int kk = 0; kk < 2; kk++) {
            const int qlog = kk * 2 + qhalf;
            uint32_t bfh[2][4], bfl[2][4];
#pragma unroll
            for (int g = 0; g < 2; g++) {
                int r = wn + g * 16 + lrow;
                uint32_t ao = (uint32_t)(r * 64 + ((qlog ^ (r & 3)) << 4));
                ldsm4(bfh[g][0], bfh[g][1], bfh[g][2], bfh[g][3], bh + ao);
                ldsm4(bfl[g][0], bfl[g][1], bfl[g][2], bfl[g][3], bl + ao);
            }
#pragma unroll
            for (int mi = 0; mi < 4; mi++) {
                int r = wm + mi * 16 + lrow;
                uint32_t ao = (uint32_t)(r * 64 + ((qlog ^ (r & 3)) << 4));
                uint32_t afh[4], afl[4];
                ldsm4(afh[0], afh[1], afh[2], afh[3], ah + ao);
                ldsm4(afl[0], afl[1], afl[2], afl[3], al + ao);
                // product-major: same-acc MMAs are 4 issues apart (no RAW chain)
#pragma unroll
                for (int ni = 0; ni < 4; ni++) {
                    const int g = ni >> 1, sub = ni & 1;
                    mma16816(acc[mi][ni], afh, bfh[g][sub], bfh[g][sub + 2]);
                }
#pragma unroll
                for (int ni = 0; ni < 4; ni++) {
                    const int g = ni >> 1, sub = ni & 1;
                    mma16816(acc[mi][ni], afh, bfl[g][sub], bfl[g][sub + 2]);
                }
#pragma unroll
                for (int ni = 0; ni < 4; ni++) {
                    const int g = ni >> 1, sub = ni & 1;
                    mma16816(acc[mi][ni], afl, bfh[g][sub], bfh[g][sub + 2]);
                }
            }
        }
        if (c + 2 < NC) issue(c + 2);
    }
    __syncthreads();

    // ---- epilogue (smem reused for staging) ----
    float* stg = (float*)dynraw;
    const int group = lane >> 2;
    const int tig   = lane & 3;

    if (G1) {
#pragma unroll
        for (int mi = 0; mi < 4; mi++) {
            int m = wm + mi * 16 + group;
#pragma unroll
            for (int ni = 0; ni < 4; ni++) {
                int j = (wid & 3) * 16 + ni * 4 + tig;
                float g0 = acc[mi][ni][0], u0 = acc[mi][ni][1];
                float g1 = acc[mi][ni][2], u1 = acc[mi][ni][3];
                stg[m * 68 + j]       = g0 / (1.f + __expf(-g0)) * u0;
                stg[(m + 8) * 68 + j] = g1 / (1.f + __expf(-g1)) * u1;
            }
        }
        __syncthreads();
#pragma unroll
        for (int t = 0; t < 8; t++) {
            int idx = tid + t * 256;
            int row = idx >> 4, q = idx & 15;
            int orow = s_out[row];
            if (orow >= 0) {
                float4 v = *(const float4*)(stg + row * 68 + q * 4);
                uint32_t h0, h1, l0, l1;
                split4(v, h0, h1, l0, l1);
                size_t ob = ((size_t)orow * F_ + bn0 + q * 4) * 2;
                *(uint2*)((char*)g_act_hi + ob) = make_uint2(h0, h1);
                *(uint2*)((char*)g_act_lo + ob) = make_uint2(l0, l1);
            }
        }
    } else {
#pragma unroll
        for (int mi = 0; mi < 4; mi++) {
            int m = wm + mi * 16 + group;
#pragma unroll
            for (int ni = 0; ni < 4; ni++) {
                int n = wn + ni * 8 + tig * 2;
                *(float2*)(stg + m * 132 + n)       = make_float2(acc[mi][ni][0], acc[mi][ni][1]);
                *(float2*)(stg + (m + 8) * 132 + n) = make_float2(acc[mi][ni][2], acc[mi][ni][3]);
            }
        }
        __syncthreads();
#pragma unroll
        for (int t = 0; t < 16; t++) {
            int idx = tid + t * 256;
            int row = idx >> 5, q = idx & 31;
            int orow = s_out[row];
            if (orow >= 0)
                *(float4*)(g_pairout + (size_t)orow * D_ + bn0 + q * 4) =
                    *(const float4*)(stg + row * 132 + q * 4);
        }
    }
}

// ---------------- weighted combine ----------------
__global__ void k_combine(const float* __restrict__ tw, float* __restrict__ out) {
    int d = blockIdx.x * 256 + threadIdx.x;
    int t = blockIdx.y;
    float w0 = tw[t * 2 + 0];
    float w1 = tw[t * 2 + 1];
    out[(size_t)t * D_ + d] =
        w0 * g_pairout[(size_t)(2 * t + 0) * D_ + d] +
        w1 * g_pairout[(size_t)(2 * t + 1) * D_ + d];
}

// ---------------- launch ----------------
extern "C" void kernel_launch(void* const* d_in, const int* in_sizes, int n_in,
                              void* d_out, int out_size) {
    const float* x   = (const float*)d_in[0];
    const float* gup = (const float*)d_in[1];
    const float* dwn = (const float*)d_in[2];
    const float* tw  = (const float*)d_in[3];
    const int*   ids = (const int*)d_in[4];
    float* out = (float*)d_out;

    cudaFuncSetAttribute(moe_gemm_mma<true>,  cudaFuncAttributeMaxDynamicSharedMemorySize, SMEM_DYN);
    cudaFuncSetAttribute(moe_gemm_mma<false>, cudaFuncAttributeMaxDynamicSharedMemorySize, SMEM_DYN);

    void *xh, *xl, *gh, *gl, *dh, *dl;
    cudaGetSymbolAddress(&xh, g_x_hi);   cudaGetSymbolAddress(&xl, g_x_lo);
    cudaGetSymbolAddress(&gh, g_gup_hi); cudaGetSymbolAddress(&gl, g_gup_lo);
    cudaGetSymbolAddress(&dh, g_dwn_hi); cudaGetSymbolAddress(&dl, g_dwn_lo);

    k_zero<<<1, 32>>>();
    k_assign<<<NP / 256, 256>>>(ids);
    k_tiles<<<1, 1>>>();
    k_rows<<<NP / 256, 256>>>();

    {
        int n4 = T_ * D_ / 4;
        k_split<<<(n4 + 255) / 256, 256>>>((const float4*)x, (uint2*)xh, (uint2*)xl, n4);
    }
    {
        int n4 = (int)((size_t)E_ * N1 * D_ / 4);
        k_split<<<(n4 + 255) / 256, 256>>>((const float4*)gup, (uint2*)gh, (uint2*)gl, n4);
    }
    {
        int n4 = (int)((size_t)E_ * D_ * F_ / 4);
        k_split<<<(n4 + 255) / 256, 256>>>((const float4*)dwn, (uint2*)dh, (uint2*)dl, n4);
    }

    moe_gemm_mma<true ><<<dim3(F_ / 64, MAXTILES), 256, SMEM_DYN>>>();
    moe_gemm_mma<false><<<dim3(D_ / 128, MAXTILES), 256, SMEM_DYN>>>();

    k_combine<<<dim3(D_ / 256, T_), 256>>>(tw, out);
}

// round 6
// speedup vs baseline: 3.3746x; 1.3552x over previous
#include <cuda_runtime.h>
#include <cuda_fp16.h>
#include <stdint.h>

// ---------------- problem constants ----------------
namespace {
constexpr int T_  = 4096;
constexpr int D_  = 1024;
constexpr int E_  = 8;
constexpr int F_  = 2816;
constexpr int NP  = T_ * 2;       // 8192 (token,k) pairs
constexpr int N1  = 2 * F_;       // 5632
constexpr int BM  = 128;
constexpr int MAXTILES = 72;

// smem: per k32-chunk buffer, 3 planes (Ah, Al, Bh) of 128x32 fp16 = 8KB each
constexpr int PL   = 8192;
constexpr int BUF  = 3 * PL;          // 24576 per buffer
constexpr int NBUF = 3;
constexpr int SMEM_DYN = NBUF * BUF;  // 73728 (>= G2 staging 128*132*4 = 67584)
}

// ---------------- device scratch (static, allocation-free) ----------------
__device__ __align__(16) __half g_x_hi[(size_t)T_ * D_];
__device__ __align__(16) __half g_x_lo[(size_t)T_ * D_];
__device__ __align__(16) __half g_gup_hi[(size_t)E_ * N1 * D_];
__device__ __align__(16) __half g_dwn_hi[(size_t)E_ * D_ * F_];
__device__ __align__(16) __half g_act_hi[(size_t)NP * F_];
__device__ __align__(16) __half g_act_lo[(size_t)NP * F_];
__device__ float g_pairout[(size_t)NP * D_];

__device__ int g_cnt[E_];
__device__ int g_off[E_ + 1];
__device__ int g_pair_e[NP];
__device__ int g_pair_slot[NP];
__device__ int g_rowtok[NP];
__device__ int g_rowpair[NP];
__device__ int g_tile_e[MAXTILES];
__device__ int g_tile_r0[MAXTILES];
__device__ int g_tile_rows[MAXTILES];
__device__ int g_ntiles;

// ---------------- helpers ----------------
__device__ __forceinline__ uint32_t smem_u32(const void* p) {
    uint32_t a;
    asm("{ .reg .u64 t; cvta.to.shared.u64 t, %1; cvt.u32.u64 %0, t; }" : "=r"(a) : "l"(p));
    return a;
}
// fp16 hi/lo split of float4: hi = rn(v), lo = rn(v - float(hi))
__device__ __forceinline__ void split4h(float4 v, uint32_t& h0, uint32_t& h1,
                                        uint32_t& l0, uint32_t& l1) {
    __half2 H0 = __floats2half2_rn(v.x, v.y);
    __half2 H1 = __floats2half2_rn(v.z, v.w);
    float2 f0 = __half22float2(H0);
    float2 f1 = __half22float2(H1);
    __half2 L0 = __floats2half2_rn(v.x - f0.x, v.y - f0.y);
    __half2 L1 = __floats2half2_rn(v.z - f1.x, v.w - f1.y);
    h0 = *(uint32_t*)&H0; h1 = *(uint32_t*)&H1;
    l0 = *(uint32_t*)&L0; l1 = *(uint32_t*)&L1;
}
__device__ __forceinline__ void hi4h(float4 v, uint32_t& h0, uint32_t& h1) {
    __half2 H0 = __floats2half2_rn(v.x, v.y);
    __half2 H1 = __floats2half2_rn(v.z, v.w);
    h0 = *(uint32_t*)&H0; h1 = *(uint32_t*)&H1;
}
__device__ __forceinline__ void ldsm4(uint32_t& r0, uint32_t& r1, uint32_t& r2, uint32_t& r3,
                                      uint32_t addr) {
    asm volatile("ldmatrix.sync.aligned.m8n8.x4.shared.b16 {%0,%1,%2,%3}, [%4];"
                 : "=r"(r0), "=r"(r1), "=r"(r2), "=r"(r3) : "r"(addr));
}
__device__ __forceinline__ void mma16816(float* c, const uint32_t* a, uint32_t b0, uint32_t b1) {
    asm volatile(
        "mma.sync.aligned.m16n8k16.row.col.f32.f16.f16.f32 "
        "{%0,%1,%2,%3}, {%4,%5,%6,%7}, {%8,%9}, {%0,%1,%2,%3};"
        : "+f"(c[0]), "+f"(c[1]), "+f"(c[2]), "+f"(c[3])
        : "r"(a[0]), "r"(a[1]), "r"(a[2]), "r"(a[3]), "r"(b0), "r"(b1));
}
__device__ __forceinline__ void cp_async16(uint32_t dst, const void* src, int sz) {
    asm volatile("cp.async.cg.shared.global [%0], [%1], 16, %2;"
                 :: "r"(dst), "l"(src), "r"(sz) : "memory");
}
__device__ __forceinline__ void cp_commit() {
    asm volatile("cp.async.commit_group;" ::: "memory");
}
__device__ __forceinline__ void cp_wait0() {
    asm volatile("cp.async.wait_group 0;" ::: "memory");
}
__device__ __forceinline__ void cp_wait1() {
    asm volatile("cp.async.wait_group 1;" ::: "memory");
}

// ---------------- routing ----------------
__global__ void k_zero() { if (threadIdx.x < E_) g_cnt[threadIdx.x] = 0; }

__global__ void k_assign(const int* __restrict__ ids) {
    int p = blockIdx.x * 256 + threadIdx.x;
    if (p >= NP) return;
    int e = ids[p];
    e = e < 0 ? 0 : (e >= E_ ? E_ - 1 : e);
    g_pair_e[p] = e;
    g_pair_slot[p] = atomicAdd(&g_cnt[e], 1);
}

__global__ void k_tiles() {
    int off = 0;
    g_off[0] = 0;
    for (int e = 0; e < E_; e++) { off += g_cnt[e]; g_off[e + 1] = off; }
    int nt = 0;
    for (int e = 0; e < E_; e++)
        for (int r0 = g_off[e]; r0 < g_off[e + 1]; r0 += BM) {
            g_tile_e[nt] = e; g_tile_r0[nt] = r0;
            int rem = g_off[e + 1] - r0;
            g_tile_rows[nt] = rem < BM ? rem : BM;
            nt++;
        }
    g_ntiles = nt;
}

__global__ void k_rows() {
    int p = blockIdx.x * 256 + threadIdx.x;
    if (p >= NP) return;
    int gr = g_off[g_pair_e[p]] + g_pair_slot[p];
    g_rowtok[gr] = p >> 1;
    g_rowpair[gr] = p;
}

// ---------------- fp32 -> fp16 pre-split kernels ----------------
__global__ void k_split2(const float4* __restrict__ src, uint2* __restrict__ hi,
                         uint2* __restrict__ lo, int n4) {
    int i = blockIdx.x * 256 + threadIdx.x;
    if (i >= n4) return;
    float4 v = src[i];
    uint32_t h0, h1, l0, l1;
    split4h(v, h0, h1, l0, l1);
    hi[i] = make_uint2(h0, h1);
    lo[i] = make_uint2(l0, l1);
}
__global__ void k_split1(const float4* __restrict__ src, uint2* __restrict__ hi, int n4) {
    int i = blockIdx.x * 256 + threadIdx.x;
    if (i >= n4) return;
    float4 v = src[i];
    uint32_t h0, h1;
    hi4h(v, h0, h1);
    hi[i] = make_uint2(h0, h1);
}

// ---------------- 2-product fp16 HMMA grouped GEMM (3-stage cp.async) ----------------
// D = Ahi.Bhi + Alo.Bhi   (B fp16-rounded; dropped A.Blo ~ 2^-12 rel)
// G1: act[row, j] = silu(x_row . gup[e, j, :]) * (x_row . gup[e, F+j, :])
//     block covers 64 j; B rows interleaved (2j = gate, 2j+1 = up)  KDIM=1024
// G2: pairout[pr, n] = act_row . down[e, n, :]  (N tile 128)        KDIM=2816
template <bool G1>
__global__ void __launch_bounds__(256, 2)
moe_gemm_mma() {
    constexpr int KDIM = G1 ? D_ : F_;
    constexpr int NC   = KDIM / 32;

    const int bt = blockIdx.y;
    if (bt >= g_ntiles) return;

    const int e    = g_tile_e[bt];
    const int row0 = g_tile_r0[bt];
    const int rows = g_tile_rows[bt];
    const int bn0  = blockIdx.x * (G1 ? 64 : 128);

    const __half* __restrict__ Ah = G1 ? g_x_hi : g_act_hi;
    const __half* __restrict__ Al = G1 ? g_x_lo : g_act_lo;
    const size_t eoff = (size_t)e * (G1 ? (size_t)N1 * D_ : (size_t)D_ * F_);
    const __half* __restrict__ Bh = (G1 ? g_gup_hi : g_dwn_hi) + eoff;

    extern __shared__ __align__(16) char dynraw[];
    const uint32_t dynbase = smem_u32(dynraw);

    __shared__ int s_map[BM];
    __shared__ int s_out[BM];

    const int tid  = threadIdx.x;
    const int wid  = tid >> 5;
    const int lane = tid & 31;

    if (tid < BM) {
        int amap = -1, omap = -1;
        if (tid < rows) {
            if (G1) { amap = g_rowtok[row0 + tid]; omap = row0 + tid; }
            else    { amap = row0 + tid;           omap = g_rowpair[row0 + tid]; }
        }
        s_map[tid] = amap; s_out[tid] = omap;
    }
    __syncthreads();

    // per-thread cp.async assignments (2 A row-units, 2 B row-units)
    const int rA0 = tid >> 2,         qA0 = tid & 3;
    const int rA1 = (tid + 256) >> 2, qA1 = tid & 3;

    auto issue = [&](int c) {
        const uint32_t base = dynbase + (uint32_t)(c % NBUF) * BUF;
        const int kofs = c * 32;
        {
            int ar = s_map[rA0];
            int sz = ar >= 0 ? 16 : 0;
            size_t so = ((size_t)(ar < 0 ? 0 : ar) * KDIM + kofs) * 2 + qA0 * 16;
            uint32_t doff = rA0 * 64 + (((uint32_t)(qA0 ^ (rA0 & 3))) << 4);
            cp_async16(base + doff,      (const char*)Ah + so, sz);
            cp_async16(base + PL + doff, (const char*)Al + so, sz);
        }
        {
            int ar = s_map[rA1];
            int sz = ar >= 0 ? 16 : 0;
            size_t so = ((size_t)(ar < 0 ? 0 : ar) * KDIM + kofs) * 2 + qA1 * 16;
            uint32_t doff = rA1 * 64 + (((uint32_t)(qA1 ^ (rA1 & 3))) << 4);
            cp_async16(base + doff,      (const char*)Ah + so, sz);
            cp_async16(base + PL + doff, (const char*)Al + so, sz);
        }
#pragma unroll
        for (int t = 0; t < 2; t++) {
            int idx = tid + t * 256;
            int row = idx >> 2, q = idx & 3;
            int brow = G1 ? (bn0 + (row >> 1) + (row & 1) * F_) : (bn0 + row);
            size_t so = ((size_t)brow * KDIM + kofs) * 2 + q * 16;
            uint32_t doff = row * 64 + (((uint32_t)(q ^ (row & 3))) << 4);
            cp_async16(base + 2 * PL + doff, (const char*)Bh + so, 16);
        }
        cp_commit();
    };

    // warp tile: 64 m x 32 n
    const int wm = (wid >> 2) * 64;
    const int wn = (wid & 3) * 32;
    const int lrow  = lane & 15;
    const int qhalf = lane >> 4;     // 0/1 -> 16B half within k32

    float acc[4][4][4];
#pragma unroll
    for (int i = 0; i < 4; i++)
#pragma unroll
        for (int j = 0; j < 4; j++)
#pragma unroll
            for (int k = 0; k < 4; k++) acc[i][j][k] = 0.f;

    issue(0);
    if (NC > 1) issue(1);

    for (int c = 0; c < NC; c++) {
        if (c + 1 < NC) cp_wait1();
        else            cp_wait0();
        __syncthreads();   // stage c visible; all warps done with stage c-1

        const uint32_t base = dynbase + (uint32_t)(c % NBUF) * BUF;
        const uint32_t ah = base, al = base + PL, bh = base + 2 * PL;

#pragma unroll
        for (int kk = 0; kk < 2; kk++) {
            const int qlog = kk * 2 + qhalf;
            uint32_t bfh[2][4];
#pragma unroll
            for (int g = 0; g < 2; g++) {
                int r = wn + g * 16 + lrow;
                uint32_t ao = (uint32_t)(r * 64 + ((qlog ^ (r & 3)) << 4));
                ldsm4(bfh[g][0], bfh[g][1], bfh[g][2], bfh[g][3], bh + ao);
            }
#pragma unroll
            for (int mi = 0; mi < 4; mi++) {
                int r = wm + mi * 16 + lrow;
                uint32_t ao = (uint32_t)(r * 64 + ((qlog ^ (r & 3)) << 4));
                uint32_t afh[4], afl[4];
                ldsm4(afh[0], afh[1], afh[2], afh[3], ah + ao);
                ldsm4(afl[0], afl[1], afl[2], afl[3], al + ao);
                // product-major: same-acc MMAs 4 issues apart
#pragma unroll
                for (int ni = 0; ni < 4; ni++) {
                    const int g = ni >> 1, sub = ni & 1;
                    mma16816(acc[mi][ni], afh, bfh[g][sub], bfh[g][sub + 2]);
                }
#pragma unroll
                for (int ni = 0; ni < 4; ni++) {
                    const int g = ni >> 1, sub = ni & 1;
                    mma16816(acc[mi][ni], afl, bfh[g][sub], bfh[g][sub + 2]);
                }
            }
        }
        if (c + 2 < NC) issue(c + 2);
    }
    __syncthreads();

    // ---- epilogue (smem reused for staging) ----
    float* stg = (float*)dynraw;
    const int group = lane >> 2;
    const int tig   = lane & 3;

    if (G1) {
#pragma unroll
        for (int mi = 0; mi < 4; mi++) {
            int m = wm + mi * 16 + group;
#pragma unroll
            for (int ni = 0; ni < 4; ni++) {
                int j = (wid & 3) * 16 + ni * 4 + tig;
                float g0 = acc[mi][ni][0], u0 = acc[mi][ni][1];
                float g1 = acc[mi][ni][2], u1 = acc[mi][ni][3];
                stg[m * 68 + j]       = g0 / (1.f + __expf(-g0)) * u0;
                stg[(m + 8) * 68 + j] = g1 / (1.f + __expf(-g1)) * u1;
            }
        }
        __syncthreads();
#pragma unroll
        for (int t = 0; t < 8; t++) {
            int idx = tid + t * 256;
            int row = idx >> 4, q = idx & 15;
            int orow = s_out[row];
            if (orow >= 0) {
                float4 v = *(const float4*)(stg + row * 68 + q * 4);
                uint32_t h0, h1, l0, l1;
                split4h(v, h0, h1, l0, l1);
                size_t ob = ((size_t)orow * F_ + bn0 + q * 4) * 2;
                *(uint2*)((char*)g_act_hi + ob) = make_uint2(h0, h1);
                *(uint2*)((char*)g_act_lo + ob) = make_uint2(l0, l1);
            }
        }
    } else {
#pragma unroll
        for (int mi = 0; mi < 4; mi++) {
            int m = wm + mi * 16 + group;
#pragma unroll
            for (int ni = 0; ni < 4; ni++) {
                int n = wn + ni * 8 + tig * 2;
                *(float2*)(stg + m * 132 + n)       = make_float2(acc[mi][ni][0], acc[mi][ni][1]);
                *(float2*)(stg + (m + 8) * 132 + n) = make_float2(acc[mi][ni][2], acc[mi][ni][3]);
            }
        }
        __syncthreads();
#pragma unroll
        for (int t = 0; t < 16; t++) {
            int idx = tid + t * 256;
            int row = idx >> 5, q = idx & 31;
            int orow = s_out[row];
            if (orow >= 0)
                *(float4*)(g_pairout + (size_t)orow * D_ + bn0 + q * 4) =
                    *(const float4*)(stg + row * 132 + q * 4);
        }
    }
}

// ---------------- weighted combine ----------------
__global__ void k_combine(const float* __restrict__ tw, float* __restrict__ out) {
    int d = blockIdx.x * 256 + threadIdx.x;
    int t = blockIdx.y;
    float w0 = tw[t * 2 + 0];
    float w1 = tw[t * 2 + 1];
    out[(size_t)t * D_ + d] =
        w0 * g_pairout[(size_t)(2 * t + 0) * D_ + d] +
        w1 * g_pairout[(size_t)(2 * t + 1) * D_ + d];
}

// ---------------- launch ----------------
extern "C" void kernel_launch(void* const* d_in, const int* in_sizes, int n_in,
                              void* d_out, int out_size) {
    const float* x   = (const float*)d_in[0];
    const float* gup = (const float*)d_in[1];
    const float* dwn = (const float*)d_in[2];
    const float* tw  = (const float*)d_in[3];
    const int*   ids = (const int*)d_in[4];
    float* out = (float*)d_out;

    cudaFuncSetAttribute(moe_gemm_mma<true>,  cudaFuncAttributeMaxDynamicSharedMemorySize, SMEM_DYN);
    cudaFuncSetAttribute(moe_gemm_mma<false>, cudaFuncAttributeMaxDynamicSharedMemorySize, SMEM_DYN);

    void *xh, *xl, *gh, *dh;
    cudaGetSymbolAddress(&xh, g_x_hi);   cudaGetSymbolAddress(&xl, g_x_lo);
    cudaGetSymbolAddress(&gh, g_gup_hi); cudaGetSymbolAddress(&dh, g_dwn_hi);

    k_zero<<<1, 32>>>();
    k_assign<<<NP / 256, 256>>>(ids);
    k_tiles<<<1, 1>>>();
    k_rows<<<NP / 256, 256>>>();

    {
        int n4 = T_ * D_ / 4;
        k_split2<<<(n4 + 255) / 256, 256>>>((const float4*)x, (uint2*)xh, (uint2*)xl, n4);
    }
    {
        int n4 = (int)((size_t)E_ * N1 * D_ / 4);
        k_split1<<<(n4 + 255) / 256, 256>>>((const float4*)gup, (uint2*)gh, n4);
    }
    {
        int n4 = (int)((size_t)E_ * D_ * F_ / 4);
        k_split1<<<(n4 + 255) / 256, 256>>>((const float4*)dwn, (uint2*)dh, n4);
    }

    moe_gemm_mma<true ><<<dim3(F_ / 64, MAXTILES), 256, SMEM_DYN>>>();
    moe_gemm_mma<false><<<dim3(D_ / 128, MAXTILES), 256, SMEM_DYN>>>();

    k_combine<<<dim3(D_ / 256, T_), 256>>>(tw, out);
}

// round 7
// speedup vs baseline: 3.3886x; 1.0042x over previous
#include <cuda_runtime.h>
#include <cuda_fp16.h>
#include <stdint.h>

// ---------------- problem constants ----------------
namespace {
constexpr int T_  = 4096;
constexpr int D_  = 1024;
constexpr int E_  = 8;
constexpr int F_  = 2816;
constexpr int NP  = T_ * 2;       // 8192 (token,k) pairs
constexpr int N1  = 2 * F_;       // 5632
constexpr int BM  = 128;
constexpr int MAXTILES = 72;

// smem: per k32-chunk buffer, 3 planes (Ah, Al, Bh) of 128x32 fp16 = 8KB each
constexpr int PL   = 8192;
constexpr int BUF  = 3 * PL;          // 24576 per buffer
constexpr int NBUF = 3;
constexpr int SMEM_DYN = NBUF * BUF;  // 73728 (>= G2 staging 128*132*4 = 67584)

// k_prep region sizes (in float4 units)
constexpr int N4_X   = T_ * D_ / 4;                         // 1,048,576
constexpr int N4_GUP = (int)((size_t)E_ * N1 * D_ / 4);     // 11,534,336
constexpr int N4_DWN = (int)((size_t)E_ * D_ * F_ / 4);     // 5,767,168
constexpr int N4_OUT = T_ * D_ / 4;                         // 1,048,576
constexpr int N4_TOTAL = N4_X + N4_GUP + N4_DWN + N4_OUT;
}

// ---------------- device scratch (static, allocation-free) ----------------
__device__ __align__(16) __half g_x_hi[(size_t)T_ * D_];
__device__ __align__(16) __half g_x_lo[(size_t)T_ * D_];
__device__ __align__(16) __half g_gup_hi[(size_t)E_ * N1 * D_];
__device__ __align__(16) __half g_dwn_hi[(size_t)E_ * D_ * F_];
__device__ __align__(16) __half g_act_hi[(size_t)NP * F_];
__device__ __align__(16) __half g_act_lo[(size_t)NP * F_];

__device__ int g_cnt[E_];
__device__ int g_off[E_ + 1];
__device__ int g_pair_e[NP];
__device__ int g_pair_slot[NP];
__device__ int g_rowtok[NP];
__device__ int g_rowpair[NP];
__device__ int g_tile_e[MAXTILES];
__device__ int g_tile_r0[MAXTILES];
__device__ int g_tile_rows[MAXTILES];
__device__ int g_ntiles;

// ---------------- helpers ----------------
__device__ __forceinline__ uint32_t smem_u32(const void* p) {
    uint32_t a;
    asm("{ .reg .u64 t; cvta.to.shared.u64 t, %1; cvt.u32.u64 %0, t; }" : "=r"(a) : "l"(p));
    return a;
}
// fp16 hi/lo split of float4: hi = rn(v), lo = rn(v - float(hi))
__device__ __forceinline__ void split4h(float4 v, uint32_t& h0, uint32_t& h1,
                                        uint32_t& l0, uint32_t& l1) {
    __half2 H0 = __floats2half2_rn(v.x, v.y);
    __half2 H1 = __floats2half2_rn(v.z, v.w);
    float2 f0 = __half22float2(H0);
    float2 f1 = __half22float2(H1);
    __half2 L0 = __floats2half2_rn(v.x - f0.x, v.y - f0.y);
    __half2 L1 = __floats2half2_rn(v.z - f1.x, v.w - f1.y);
    h0 = *(uint32_t*)&H0; h1 = *(uint32_t*)&H1;
    l0 = *(uint32_t*)&L0; l1 = *(uint32_t*)&L1;
}
__device__ __forceinline__ void hi4h(float4 v, uint32_t& h0, uint32_t& h1) {
    __half2 H0 = __floats2half2_rn(v.x, v.y);
    __half2 H1 = __floats2half2_rn(v.z, v.w);
    h0 = *(uint32_t*)&H0; h1 = *(uint32_t*)&H1;
}
__device__ __forceinline__ void ldsm4(uint32_t& r0, uint32_t& r1, uint32_t& r2, uint32_t& r3,
                                      uint32_t addr) {
    asm volatile("ldmatrix.sync.aligned.m8n8.x4.shared.b16 {%0,%1,%2,%3}, [%4];"
                 : "=r"(r0), "=r"(r1), "=r"(r2), "=r"(r3) : "r"(addr));
}
__device__ __forceinline__ void mma16816(float* c, const uint32_t* a, uint32_t b0, uint32_t b1) {
    asm volatile(
        "mma.sync.aligned.m16n8k16.row.col.f32.f16.f16.f32 "
        "{%0,%1,%2,%3}, {%4,%5,%6,%7}, {%8,%9}, {%0,%1,%2,%3};"
        : "+f"(c[0]), "+f"(c[1]), "+f"(c[2]), "+f"(c[3])
        : "r"(a[0]), "r"(a[1]), "r"(a[2]), "r"(a[3]), "r"(b0), "r"(b1));
}
__device__ __forceinline__ void cp_async16(uint32_t dst, const void* src, int sz) {
    asm volatile("cp.async.cg.shared.global [%0], [%1], 16, %2;"
                 :: "r"(dst), "l"(src), "r"(sz) : "memory");
}
__device__ __forceinline__ void cp_commit() {
    asm volatile("cp.async.commit_group;" ::: "memory");
}
__device__ __forceinline__ void cp_wait0() {
    asm volatile("cp.async.wait_group 0;" ::: "memory");
}
__device__ __forceinline__ void cp_wait1() {
    asm volatile("cp.async.wait_group 1;" ::: "memory");
}
__device__ __forceinline__ void redadd(float* p, float v) {
    asm volatile("red.global.add.f32 [%0], %1;" :: "l"(p), "f"(v) : "memory");
}

// ---------------- routing ----------------
__global__ void k_zero() { if (threadIdx.x < E_) g_cnt[threadIdx.x] = 0; }

__global__ void k_assign(const int* __restrict__ ids) {
    int p = blockIdx.x * 256 + threadIdx.x;
    if (p >= NP) return;
    int e = ids[p];
    e = e < 0 ? 0 : (e >= E_ ? E_ - 1 : e);
    g_pair_e[p] = e;
    g_pair_slot[p] = atomicAdd(&g_cnt[e], 1);
}

__global__ void k_tiles() {
    int off = 0;
    g_off[0] = 0;
    for (int e = 0; e < E_; e++) { off += g_cnt[e]; g_off[e + 1] = off; }
    int nt = 0;
    for (int e = 0; e < E_; e++)
        for (int r0 = g_off[e]; r0 < g_off[e + 1]; r0 += BM) {
            g_tile_e[nt] = e; g_tile_r0[nt] = r0;
            int rem = g_off[e + 1] - r0;
            g_tile_rows[nt] = rem < BM ? rem : BM;
            nt++;
        }
    g_ntiles = nt;
}

__global__ void k_rows() {
    int p = blockIdx.x * 256 + threadIdx.x;
    if (p >= NP) return;
    int gr = g_off[g_pair_e[p]] + g_pair_slot[p];
    g_rowtok[gr] = p >> 1;
    g_rowpair[gr] = p;
}

// ---------------- merged prep: fp32->fp16 splits + d_out zeroing ----------------
__global__ void k_prep(const float4* __restrict__ x, const float4* __restrict__ gup,
                       const float4* __restrict__ dwn, float4* __restrict__ out) {
    int i = blockIdx.x * 256 + threadIdx.x;
    if (i < N4_X) {
        float4 v = x[i];
        uint32_t h0, h1, l0, l1;
        split4h(v, h0, h1, l0, l1);
        ((uint2*)g_x_hi)[i] = make_uint2(h0, h1);
        ((uint2*)g_x_lo)[i] = make_uint2(l0, l1);
        return;
    }
    i -= N4_X;
    if (i < N4_GUP) {
        float4 v = gup[i];
        uint32_t h0, h1;
        hi4h(v, h0, h1);
        ((uint2*)g_gup_hi)[i] = make_uint2(h0, h1);
        return;
    }
    i -= N4_GUP;
    if (i < N4_DWN) {
        float4 v = dwn[i];
        uint32_t h0, h1;
        hi4h(v, h0, h1);
        ((uint2*)g_dwn_hi)[i] = make_uint2(h0, h1);
        return;
    }
    i -= N4_DWN;
    if (i < N4_OUT) out[i] = make_float4(0.f, 0.f, 0.f, 0.f);
}

// ---------------- 2-product fp16 HMMA grouped GEMM (3-stage cp.async) ----------------
// D = Ahi.Bhi + Alo.Bhi   (B fp16-rounded; dropped A.Blo ~ 2^-12 rel)
// G1: act[row, j] = silu(x_row . gup[e, j, :]) * (x_row . gup[e, F+j, :])
//     block covers 64 j; B rows interleaved (2j = gate, 2j+1 = up)  KDIM=1024
// G2: out[tok, n] += w_pair * (act_row . down[e, n, :])  (N tile 128) KDIM=2816
template <bool G1>
__global__ void __launch_bounds__(256, 2)
moe_gemm_mma(const float* __restrict__ tw, float* __restrict__ outp) {
    constexpr int KDIM = G1 ? D_ : F_;
    constexpr int NC   = KDIM / 32;

    const int bt = blockIdx.y;
    if (bt >= g_ntiles) return;

    const int e    = g_tile_e[bt];
    const int row0 = g_tile_r0[bt];
    const int rows = g_tile_rows[bt];
    const int bn0  = blockIdx.x * (G1 ? 64 : 128);

    const __half* __restrict__ Ah = G1 ? g_x_hi : g_act_hi;
    const __half* __restrict__ Al = G1 ? g_x_lo : g_act_lo;
    const size_t eoff = (size_t)e * (G1 ? (size_t)N1 * D_ : (size_t)D_ * F_);
    const __half* __restrict__ Bh = (G1 ? g_gup_hi : g_dwn_hi) + eoff;

    extern __shared__ __align__(16) char dynraw[];
    const uint32_t dynbase = smem_u32(dynraw);

    __shared__ int   s_map[BM];
    __shared__ int   s_out[BM];
    __shared__ float s_wt[BM];

    const int tid  = threadIdx.x;
    const int wid  = tid >> 5;
    const int lane = tid & 31;

    if (tid < BM) {
        int amap = -1, omap = -1;
        float w = 0.f;
        if (tid < rows) {
            if (G1) { amap = g_rowtok[row0 + tid]; omap = row0 + tid; }
            else    { amap = row0 + tid;           omap = g_rowpair[row0 + tid];
                      w = tw[omap]; }
        }
        s_map[tid] = amap; s_out[tid] = omap; s_wt[tid] = w;
    }
    __syncthreads();

    // per-thread cp.async assignments (2 A row-units, 2 B row-units)
    const int rA0 = tid >> 2,         qA0 = tid & 3;
    const int rA1 = (tid + 256) >> 2, qA1 = tid & 3;

    auto issue = [&](int c) {
        const uint32_t base = dynbase + (uint32_t)(c % NBUF) * BUF;
        const int kofs = c * 32;
        {
            int ar = s_map[rA0];
            int sz = ar >= 0 ? 16 : 0;
            size_t so = ((size_t)(ar < 0 ? 0 : ar) * KDIM + kofs) * 2 + qA0 * 16;
            uint32_t doff = rA0 * 64 + (((uint32_t)(qA0 ^ (rA0 & 3))) << 4);
            cp_async16(base + doff,      (const char*)Ah + so, sz);
            cp_async16(base + PL + doff, (const char*)Al + so, sz);
        }
        {
            int ar = s_map[rA1];
            int sz = ar >= 0 ? 16 : 0;
            size_t so = ((size_t)(ar < 0 ? 0 : ar) * KDIM + kofs) * 2 + qA1 * 16;
            uint32_t doff = rA1 * 64 + (((uint32_t)(qA1 ^ (rA1 & 3))) << 4);
            cp_async16(base + doff,      (const char*)Ah + so, sz);
            cp_async16(base + PL + doff, (const char*)Al + so, sz);
        }
#pragma unroll
        for (int t = 0; t < 2; t++) {
            int idx = tid + t * 256;
            int row = idx >> 2, q = idx & 3;
            int brow = G1 ? (bn0 + (row >> 1) + (row & 1) * F_) : (bn0 + row);
            size_t so = ((size_t)brow * KDIM + kofs) * 2 + q * 16;
            uint32_t doff = row * 64 + (((uint32_t)(q ^ (row & 3))) << 4);
            cp_async16(base + 2 * PL + doff, (const char*)Bh + so, 16);
        }
        cp_commit();
    };

    // warp tile: 64 m x 32 n
    const int wm = (wid >> 2) * 64;
    const int wn = (wid & 3) * 32;
    const int lrow  = lane & 15;
    const int qhalf = lane >> 4;     // 0/1 -> 16B half within k32

    float acc[4][4][4];
#pragma unroll
    for (int i = 0; i < 4; i++)
#pragma unroll
        for (int j = 0; j < 4; j++)
#pragma unroll
            for (int k = 0; k < 4; k++) acc[i][j][k] = 0.f;

    issue(0);
    if (NC > 1) issue(1);

    for (int c = 0; c < NC; c++) {
        if (c + 1 < NC) cp_wait1();
        else            cp_wait0();
        __syncthreads();   // stage c visible; all warps done with stage c-1

        const uint32_t base = dynbase + (uint32_t)(c % NBUF) * BUF;
        const uint32_t ah = base, al = base + PL, bh = base + 2 * PL;

#pragma unroll
        for (int kk = 0; kk < 2; kk++) {
            const int qlog = kk * 2 + qhalf;
            uint32_t bfh[2][4];
#pragma unroll
            for (int g = 0; g < 2; g++) {
                int r = wn + g * 16 + lrow;
                uint32_t ao = (uint32_t)(r * 64 + ((qlog ^ (r & 3)) << 4));
                ldsm4(bfh[g][0], bfh[g][1], bfh[g][2], bfh[g][3], bh + ao);
            }
#pragma unroll
            for (int mi = 0; mi < 4; mi++) {
                int r = wm + mi * 16 + lrow;
                uint32_t ao = (uint32_t)(r * 64 + ((qlog ^ (r & 3)) << 4));
                uint32_t afh[4], afl[4];
                ldsm4(afh[0], afh[1], afh[2], afh[3], ah + ao);
                ldsm4(afl[0], afl[1], afl[2], afl[3], al + ao);
                // product-major: same-acc MMAs 4 issues apart
#pragma unroll
                for (int ni = 0; ni < 4; ni++) {
                    const int g = ni >> 1, sub = ni & 1;
                    mma16816(acc[mi][ni], afh, bfh[g][sub], bfh[g][sub + 2]);
                }
#pragma unroll
                for (int ni = 0; ni < 4; ni++) {
                    const int g = ni >> 1, sub = ni & 1;
                    mma16816(acc[mi][ni], afl, bfh[g][sub], bfh[g][sub + 2]);
                }
            }
        }
        if (c + 2 < NC) issue(c + 2);
    }
    __syncthreads();

    // ---- epilogue (smem reused for staging) ----
    float* stg = (float*)dynraw;
    const int group = lane >> 2;
    const int tig   = lane & 3;

    if (G1) {
#pragma unroll
        for (int mi = 0; mi < 4; mi++) {
            int m = wm + mi * 16 + group;
#pragma unroll
            for (int ni = 0; ni < 4; ni++) {
                int j = (wid & 3) * 16 + ni * 4 + tig;
                float g0 = acc[mi][ni][0], u0 = acc[mi][ni][1];
                float g1 = acc[mi][ni][2], u1 = acc[mi][ni][3];
                stg[m * 68 + j]       = g0 / (1.f + __expf(-g0)) * u0;
                stg[(m + 8) * 68 + j] = g1 / (1.f + __expf(-g1)) * u1;
            }
        }
        __syncthreads();
#pragma unroll
        for (int t = 0; t < 8; t++) {
            int idx = tid + t * 256;
            int row = idx >> 4, q = idx & 15;
            int orow = s_out[row];
            if (orow >= 0) {
                float4 v = *(const float4*)(stg + row * 68 + q * 4);
                uint32_t h0, h1, l0, l1;
                split4h(v, h0, h1, l0, l1);
                size_t ob = ((size_t)orow * F_ + bn0 + q * 4) * 2;
                *(uint2*)((char*)g_act_hi + ob) = make_uint2(h0, h1);
                *(uint2*)((char*)g_act_lo + ob) = make_uint2(l0, l1);
            }
        }
    } else {
        // stage C, then weighted red.global.add into out[tok] (2 contributions
        // per element, fp32 add commutative -> deterministic)
#pragma unroll
        for (int mi = 0; mi < 4; mi++) {
            int m = wm + mi * 16 + group;
#pragma unroll
            for (int ni = 0; ni < 4; ni++) {
                int n = wn + ni * 8 + tig * 2;
                *(float2*)(stg + m * 132 + n)       = make_float2(acc[mi][ni][0], acc[mi][ni][1]);
                *(float2*)(stg + (m + 8) * 132 + n) = make_float2(acc[mi][ni][2], acc[mi][ni][3]);
            }
        }
        __syncthreads();
#pragma unroll
        for (int t = 0; t < 16; t++) {
            int idx = tid + t * 256;
            int row = idx >> 5, q = idx & 31;
            int orow = s_out[row];
            if (orow >= 0) {
                float4 v = *(const float4*)(stg + row * 132 + q * 4);
                float w = s_wt[row];
                float* op = outp + (size_t)(orow >> 1) * D_ + bn0 + q * 4;
                redadd(op + 0, w * v.x);
                redadd(op + 1, w * v.y);
                redadd(op + 2, w * v.z);
                redadd(op + 3, w * v.w);
            }
        }
    }
}

// ---------------- launch ----------------
extern "C" void kernel_launch(void* const* d_in, const int* in_sizes, int n_in,
                              void* d_out, int out_size) {
    const float* x   = (const float*)d_in[0];
    const float* gup = (const float*)d_in[1];
    const float* dwn = (const float*)d_in[2];
    const float* tw  = (const float*)d_in[3];
    const int*   ids = (const int*)d_in[4];
    float* out = (float*)d_out;

    cudaFuncSetAttribute(moe_gemm_mma<true>,  cudaFuncAttributeMaxDynamicSharedMemorySize, SMEM_DYN);
    cudaFuncSetAttribute(moe_gemm_mma<false>, cudaFuncAttributeMaxDynamicSharedMemorySize, SMEM_DYN);

    k_zero<<<1, 32>>>();
    k_assign<<<NP / 256, 256>>>(ids);
    k_tiles<<<1, 1>>>();
    k_rows<<<NP / 256, 256>>>();

    k_prep<<<(N4_TOTAL + 255) / 256, 256>>>((const float4*)x, (const float4*)gup,
                                            (const float4*)dwn, (float4*)out);

    moe_gemm_mma<true ><<<dim3(F_ / 64, MAXTILES), 256, SMEM_DYN>>>(tw, out);
    moe_gemm_mma<false><<<dim3(D_ / 128, MAXTILES), 256, SMEM_DYN>>>(tw, out);
}